// round 1
// baseline (speedup 1.0000x reference)
#include <cuda_runtime.h>

// Problem constants
#define NPIX   65536          // 256*256
#define DH     64             // histogram bins
#define PB     16             // pixels staged per SMEM round
#define NCHUNK 18             // pixel chunks per (img,b)  -> 16*18 = 288 CTAs (one wave at 2 CTA/SM)
#define CPX    ((NPIX + NCHUNK - 1) / NCHUNK)

// Scratch (allocation-free rule: __device__ globals)
__device__ float g_hist[2 * 8 * 3 * DH * DH];   // [img][b][ch][64][64]
__device__ float g_hn[8];

__device__ __forceinline__ float frcp(float x) {
    float r; asm("rcp.approx.f32 %0, %1;" : "=f"(r) : "f"(x)); return r;
}
__device__ __forceinline__ float plo(unsigned long long v) {
    return __uint_as_float((unsigned int)(v & 0xffffffffull));
}
__device__ __forceinline__ float phi(unsigned long long v) {
    return __uint_as_float((unsigned int)(v >> 32));
}

#define FFMA2(acc, a, b) asm("fma.rn.f32x2 %0, %1, %2, %0;" : "+l"(acc) : "l"(a), "l"(b))
#define MUL2(d, a, b)    asm("mul.rn.f32x2 %0, %1, %2;"      : "=l"(d)  : "l"(a), "l"(b))

// ---------------------------------------------------------------------------
// Kernel 0: zero the histogram scratch (graph replays require re-zeroing)
// ---------------------------------------------------------------------------
__global__ void zero_kernel() {
    int i = blockIdx.x * blockDim.x + threadIdx.x;   // grid sized exactly
    g_hist[i] = 0.0f;
}

// ---------------------------------------------------------------------------
// Kernel 1: histogram accumulation.
// Each CTA: one (img, batch) and a pixel chunk. 256 threads, each owns a
// 2-row x 8-col tile of the 64x64 hist for all 3 channels, packed as f32x2.
//
// Channel identities (centers symmetric: c_i = -c_{63-i}):
//   hist_r[u][v] = sum iy * rbf(ur)[u]      * rbf(vr)[v]
//   hist_g[u][v] = sum iy * rbf(ur)[63-u]   * rbf(w)[v]      (w = lg - lb)
//   hist_b[u][v] = sum iy * rbf(vr)[63-u]   * rbf(w)[63-v]
// ---------------------------------------------------------------------------
__global__ void __launch_bounds__(256, 2)
hist_kernel(const float* __restrict__ x, const float* __restrict__ y) {
    int combo = blockIdx.x / NCHUNK;
    int chunk = blockIdx.x % NCHUNK;
    int img = combo >> 3;
    int b   = combo & 7;
    const float* src = img ? y : x;
    const float* pr = src + (size_t)(b * 3 + 0) * NPIX;
    const float* pg = src + (size_t)(b * 3 + 1) * NPIX;
    const float* pbl = src + (size_t)(b * 3 + 2) * NPIX;

    int cs = chunk * CPX;
    int ce = cs + CPX; if (ce > NPIX) ce = NPIX;

    // SMEM staging. "2" arrays hold each value DUPLICATED (broadcast pairs for f32x2).
    __shared__ float  s_su2[PB][128];   // iy * rbf(ur), duplicated
    __shared__ float  s_sv2[PB][128];   // rbf(vr), duplicated
    __shared__ float  s_sv [PB][64];    // rbf(vr), natural
    __shared__ float  s_w  [PB][64];    // rbf(w),  natural
    __shared__ float  s_iy2[PB][2];     // iy duplicated
    __shared__ float4 s_px [PB];        // (ur, vr, w, iy)

    const int tid = threadIdx.x;
    const int ty  = tid >> 3;     // 0..31 -> rows 2*ty, 2*ty+1
    const int tx  = tid & 7;      // 0..7  -> cols 8*tx .. 8*tx+7
    const int cb  = tx * 8;

    unsigned long long accR[2][4], accG[2][4], accB[2][4];
#pragma unroll
    for (int k = 0; k < 2; k++)
#pragma unroll
        for (int m = 0; m < 4; m++) { accR[k][m] = 0ull; accG[k][m] = 0ull; accB[k][m] = 0ull; }

    for (int base = cs; base < ce; base += PB) {
        // ---- Stage A: per-pixel preprocessing (16 threads) ----
        if (tid < PB) {
            int n = base + tid;
            float ur = 0.f, vr = 0.f, wv = 0.f, iy = 0.f;
            if (n < ce) {
                float r  = pr[n]  + 1e-6f;
                float g  = pg[n]  + 1e-6f;
                float bb = pbl[n] + 1e-6f;
                float lr = __logf(r), lg = __logf(g), lb = __logf(bb);
                ur = lr - lg;
                vr = lr - lb;
                wv = lg - lb;
                iy = sqrtf(fmaf(r, r, fmaf(g, g, bb * bb)));
            }
            s_px[tid] = make_float4(ur, vr, wv, iy);   // iy=0 pad => zero contribution
        }
        __syncthreads();

        // ---- Stage B: RBF evaluation (16 threads per pixel, 4 bins each) ----
        {
            int p  = tid >> 4;
            int l0 = (tid & 15) << 2;
            float4 px = s_px[p];
#pragma unroll
            for (int k = 0; k < 4; k++) {
                int i = l0 + k;
                float c50 = fmaf((float)i, 300.0f / 63.0f, -150.0f);  // 50 * center_i
                float tu = fmaf(px.x, 50.0f, -c50);
                float su = px.w * frcp(fmaf(tu, tu, 1.0f));
                float tv = fmaf(px.y, 50.0f, -c50);
                float sv = frcp(fmaf(tv, tv, 1.0f));
                float tw = fmaf(px.z, 50.0f, -c50);
                float sw = frcp(fmaf(tw, tw, 1.0f));
                s_sv[p][i] = sv;
                s_w [p][i] = sw;
                *(float2*)&s_su2[p][2 * i] = make_float2(su, su);
                *(float2*)&s_sv2[p][2 * i] = make_float2(sv, sv);
            }
            if ((tid & 15) == 0) *(float2*)&s_iy2[p][0] = make_float2(px.w, px.w);
        }
        __syncthreads();

        // ---- Stage C: outer-product accumulate (f32x2) ----
#pragma unroll 1
        for (int p = 0; p < PB; p++) {
            const float* su2p = s_su2[p];
            const float* sv2p = s_sv2[p];
            const float* svp  = s_sv[p];
            const float* wp   = s_w[p];

            // Row (broadcast) operands, already duplicated pairs.
            ulonglong2 au  = *(const ulonglong2*)(su2p + 4 * ty);         // .x=row 2ty, .y=row 2ty+1
            ulonglong2 aug = *(const ulonglong2*)(su2p + 124 - 4 * ty);   // reversed: .y=row 2ty, .x=row 2ty+1
            ulonglong2 abr = *(const ulonglong2*)(sv2p + 124 - 4 * ty);   // reversed rbf(vr)
            unsigned long long iyp = *(const unsigned long long*)(&s_iy2[p][0]);
            unsigned long long aB0, aB1;
            MUL2(aB0, abr.y, iyp);    // row 2ty
            MUL2(aB1, abr.x, iyp);    // row 2ty+1

            // Column (pair) operands.
            ulonglong2 bv0 = *(const ulonglong2*)(svp + cb);
            ulonglong2 bv1 = *(const ulonglong2*)(svp + cb + 4);
            ulonglong2 bw0 = *(const ulonglong2*)(wp + cb);
            ulonglong2 bw1 = *(const ulonglong2*)(wp + cb + 4);
            ulonglong2 br0 = *(const ulonglong2*)(wp + 56 - cb);          // reversed cols (swapped in-pair)
            ulonglong2 br1 = *(const ulonglong2*)(wp + 60 - cb);

            unsigned long long aU[2] = { au.x,  au.y  };
            unsigned long long aG[2] = { aug.y, aug.x };
            unsigned long long aB[2] = { aB0,   aB1   };
            unsigned long long bV[4] = { bv0.x, bv0.y, bv1.x, bv1.y };
            unsigned long long bW[4] = { bw0.x, bw0.y, bw1.x, bw1.y };
            unsigned long long bR[4] = { br0.x, br0.y, br1.x, br1.y };

#pragma unroll
            for (int k = 0; k < 2; k++) {
#pragma unroll
                for (int m = 0; m < 4; m++) {
                    FFMA2(accR[k][m], aU[k], bV[m]);
                    FFMA2(accG[k][m], aG[k], bW[m]);
                    FFMA2(accB[k][m], aB[k], bR[m]);
                }
            }
        }
        __syncthreads();
    }

    // ---- Writeout: atomic reduce into global hist ----
    size_t basec = ((size_t)(img * 8 + b)) * 3 * 4096;
    float* hR = g_hist + basec;
    float* hG = g_hist + basec + 4096;
    float* hB = g_hist + basec + 8192;
    int row0 = 2 * ty;
#pragma unroll
    for (int k = 0; k < 2; k++) {
        int ro = (row0 + k) * 64 + cb;
#pragma unroll
        for (int m = 0; m < 4; m++) {
            atomicAdd(hR + ro + 2 * m,     plo(accR[k][m]));
            atomicAdd(hR + ro + 2 * m + 1, phi(accR[k][m]));
            atomicAdd(hG + ro + 2 * m,     plo(accG[k][m]));
            atomicAdd(hG + ro + 2 * m + 1, phi(accG[k][m]));
            // reversed-column channel: pair s covers cols (cb+7-2m) [lo], (cb+6-2m) [hi]
            atomicAdd(hB + ro + 7 - 2 * m, plo(accB[k][m]));
            atomicAdd(hB + ro + 6 - 2 * m, phi(accB[k][m]));
        }
    }
}

// ---------------------------------------------------------------------------
// Kernel 2: per-batch normalize + Hellinger-style distance
// ---------------------------------------------------------------------------
__global__ void loss_kernel() {
    int b = blockIdx.x;                     // 0..7
    const float* hx = g_hist + (size_t)b * 12288;         // img 0
    const float* hy = g_hist + (size_t)(8 + b) * 12288;   // img 1
    __shared__ float red[256];
    int tid = threadIdx.x;

    float sx = 0.f, sy = 0.f;
    for (int i = tid; i < 12288; i += 256) { sx += hx[i]; sy += hy[i]; }

    red[tid] = sx; __syncthreads();
    for (int s = 128; s > 0; s >>= 1) { if (tid < s) red[tid] += red[tid + s]; __syncthreads(); }
    float Tx = red[0]; __syncthreads();

    red[tid] = sy; __syncthreads();
    for (int s = 128; s > 0; s >>= 1) { if (tid < s) red[tid] += red[tid + s]; __syncthreads(); }
    float Ty = red[0]; __syncthreads();

    float ivx = 1.0f / Tx, ivy = 1.0f / Ty;
    float acc = 0.f;
    for (int i = tid; i < 12288; i += 256) {
        float d = sqrtf(hy[i] * ivy) - sqrtf(hx[i] * ivx);
        acc = fmaf(d, d, acc);
    }
    red[tid] = acc; __syncthreads();
    for (int s = 128; s > 0; s >>= 1) { if (tid < s) red[tid] += red[tid + s]; __syncthreads(); }
    if (tid == 0) g_hn[b] = sqrtf(red[0] * 0.5f);
}

// ---------------------------------------------------------------------------
// Kernel 3: mean over batch
// ---------------------------------------------------------------------------
__global__ void final_kernel(float* out) {
    if (threadIdx.x == 0) {
        float s = 0.f;
#pragma unroll
        for (int i = 0; i < 8; i++) s += g_hn[i];
        out[0] = s * 0.125f;
    }
}

// ---------------------------------------------------------------------------
extern "C" void kernel_launch(void* const* d_in, const int* in_sizes, int n_in,
                              void* d_out, int out_size) {
    const float* x = (const float*)d_in[0];
    const float* y = (const float*)d_in[1];

    zero_kernel<<<1536, 256>>>();                       // 1536*256 == 2*8*3*64*64
    hist_kernel<<<16 * NCHUNK, 256>>>(x, y);
    loss_kernel<<<8, 256>>>();
    final_kernel<<<1, 32>>>((float*)d_out);
}

// round 2
// speedup vs baseline: 1.1994x; 1.1994x over previous
#include <cuda_runtime.h>

// Problem constants
#define NPIX   65536          // 256*256
#define DH     64             // histogram bins
#define PB     16             // pixels staged per SMEM round
#define NCHUNK 18             // pixel chunks per (img,b)  -> 16*18 = 288 CTAs (one wave at 2 CTA/SM)
#define CPX    ((NPIX + NCHUNK - 1) / NCHUNK)
#define HISTN  (2 * 8 * 3 * DH * DH)

// Scratch (allocation-free rule: __device__ globals)
__device__ float g_hist[HISTN];   // [img][b][ch][64][64]
__device__ float g_hn[8];

__device__ __forceinline__ float frcp(float x) {
    float r; asm("rcp.approx.f32 %0, %1;" : "=f"(r) : "f"(x)); return r;
}
__device__ __forceinline__ float plo(unsigned long long v) {
    return __uint_as_float((unsigned int)(v & 0xffffffffull));
}
__device__ __forceinline__ float phi(unsigned long long v) {
    return __uint_as_float((unsigned int)(v >> 32));
}

#define FFMA2(acc, a, b) asm("fma.rn.f32x2 %0, %1, %2, %0;" : "+l"(acc) : "l"(a), "l"(b))

// ---------------------------------------------------------------------------
// Kernel 0: zero a slice of the histogram scratch (split into 3 launches so
// hist_kernel lands at global launch index 5 for the ncu -s 5 -c 1 capture).
// ---------------------------------------------------------------------------
__global__ void zero_kernel(int off) {
    int i = off + blockIdx.x * blockDim.x + threadIdx.x;
    if (i < HISTN) g_hist[i] = 0.0f;
}

// ---------------------------------------------------------------------------
// Kernel 1: histogram accumulation.
// Each CTA: one (img, batch) and a pixel chunk. 256 threads; thread (ty,tx)
// owns rows {2ty, 2ty+1} and cols {4tx..4tx+3, 32+4tx..32+4tx+3} of the
// 64x64 hist, for all 3 channels, packed as f32x2 accumulators.
//
// Channel identities (centers symmetric: c_i = -c_{63-i}), with
//   U = iy*rbf(ur), Vi = iy*rbf(vr), V = rbf(vr), W = rbf(lg-lb):
//   accR[r][c] = sum U[r]*V[c]  = hist_r[r][c]
//   accG[r][c] = sum U[r]*W[c]  = hist_g[63-r][c]     (reverse rows at writeout)
//   accB[r][c] = sum Vi[r]*W[c] = hist_b[63-r][63-c]  (reverse both at writeout)
// ---------------------------------------------------------------------------
__global__ void __launch_bounds__(256, 2)
hist_kernel(const float* __restrict__ x, const float* __restrict__ y) {
    int combo = blockIdx.x / NCHUNK;
    int chunk = blockIdx.x % NCHUNK;
    int img = combo >> 3;
    int b   = combo & 7;
    const float* src = img ? y : x;
    const float* pr  = src + (size_t)(b * 3 + 0) * NPIX;
    const float* pg  = src + (size_t)(b * 3 + 1) * NPIX;
    const float* pbl = src + (size_t)(b * 3 + 2) * NPIX;

    int cs = chunk * CPX;
    int ce = cs + CPX; if (ce > NPIX) ce = NPIX;

    // SMEM staging. "2" arrays hold each value DUPLICATED (broadcast pairs for f32x2).
    __shared__ float  s_su2 [PB][128];  // U  = iy*rbf(ur), duplicated
    __shared__ float  s_svi2[PB][128];  // Vi = iy*rbf(vr), duplicated
    __shared__ float  s_sv  [PB][64];   // V  = rbf(vr), natural order
    __shared__ float  s_w   [PB][64];   // W  = rbf(lg-lb), natural order
    __shared__ float4 s_px  [PB];       // (ur, vr, w, iy)

    const int tid = threadIdx.x;
    const int ty  = tid >> 3;     // 0..31 -> rows 2*ty, 2*ty+1
    const int tx  = tid & 7;      // 0..7  -> cols 4*tx.. and 32+4*tx..

    unsigned long long accR[2][4], accG[2][4], accB[2][4];
#pragma unroll
    for (int k = 0; k < 2; k++)
#pragma unroll
        for (int m = 0; m < 4; m++) { accR[k][m] = 0ull; accG[k][m] = 0ull; accB[k][m] = 0ull; }

    for (int base = cs; base < ce; base += PB) {
        // ---- Stage A: per-pixel preprocessing (16 threads) ----
        if (tid < PB) {
            int n = base + tid;
            float ur = 0.f, vr = 0.f, wv = 0.f, iy = 0.f;
            if (n < ce) {
                float r  = pr[n]  + 1e-6f;
                float g  = pg[n]  + 1e-6f;
                float bb = pbl[n] + 1e-6f;
                float lr = __logf(r), lg = __logf(g), lb = __logf(bb);
                ur = lr - lg;
                vr = lr - lb;
                wv = lg - lb;
                iy = sqrtf(fmaf(r, r, fmaf(g, g, bb * bb)));
            }
            s_px[tid] = make_float4(ur, vr, wv, iy);   // iy=0 pad => zero contribution
        }
        __syncthreads();

        // ---- Stage B: RBF evaluation (16 threads per pixel, 4 bins each) ----
        {
            int p  = tid >> 4;
            int l0 = (tid & 15) << 2;
            float4 px = s_px[p];
#pragma unroll
            for (int k = 0; k < 4; k++) {
                int i = l0 + k;
                float c50 = fmaf((float)i, 300.0f / 63.0f, -150.0f);  // 50 * center_i
                float tu = fmaf(px.x, 50.0f, -c50);
                float su = px.w * frcp(fmaf(tu, tu, 1.0f));           // U
                float tv = fmaf(px.y, 50.0f, -c50);
                float sv = frcp(fmaf(tv, tv, 1.0f));                  // V
                float tw = fmaf(px.z, 50.0f, -c50);
                float sw = frcp(fmaf(tw, tw, 1.0f));                  // W
                s_sv[p][i] = sv;
                s_w [p][i] = sw;
                *(float2*)&s_su2 [p][2 * i] = make_float2(su, su);
                *(float2*)&s_svi2[p][2 * i] = make_float2(px.w * sv, px.w * sv);  // Vi
            }
        }
        __syncthreads();

        // ---- Stage C: outer-product accumulate (f32x2), conflict-free LDS ----
        const float* su2p = &s_su2 [0][0] + 4 * ty;
        const float* svi2p= &s_svi2[0][0] + 4 * ty;
        const float* svp  = &s_sv  [0][0] + 4 * tx;
        const float* wp   = &s_w   [0][0] + 4 * tx;
#pragma unroll 1
        for (int p = 0; p < PB; p++) {
            // Row (broadcast) operands: duplicated pairs, rows 2ty (x) and 2ty+1 (y).
            ulonglong2 aU  = *(const ulonglong2*)(su2p  + p * 128);
            ulonglong2 aVi = *(const ulonglong2*)(svi2p + p * 128);
            // Column (pair) operands: 16B-stride across tx -> zero bank conflicts.
            ulonglong2 bv0 = *(const ulonglong2*)(svp + p * 64);        // cols 4tx..4tx+3
            ulonglong2 bv1 = *(const ulonglong2*)(svp + p * 64 + 32);   // cols 32+4tx..
            ulonglong2 bw0 = *(const ulonglong2*)(wp  + p * 64);
            ulonglong2 bw1 = *(const ulonglong2*)(wp  + p * 64 + 32);

            unsigned long long rU[2]  = { aU.x,  aU.y  };
            unsigned long long rVi[2] = { aVi.x, aVi.y };
            unsigned long long cV[4]  = { bv0.x, bv0.y, bv1.x, bv1.y };
            unsigned long long cW[4]  = { bw0.x, bw0.y, bw1.x, bw1.y };

#pragma unroll
            for (int k = 0; k < 2; k++) {
#pragma unroll
                for (int m = 0; m < 4; m++) {
                    FFMA2(accR[k][m], rU[k],  cV[m]);
                    FFMA2(accG[k][m], rU[k],  cW[m]);
                    FFMA2(accB[k][m], rVi[k], cW[m]);
                }
            }
        }
        __syncthreads();
    }

    // ---- Writeout: atomic reduce into global hist (reversals applied here) ----
    size_t basec = ((size_t)(img * 8 + b)) * 3 * 4096;
    float* hR = g_hist + basec;
    float* hG = g_hist + basec + 4096;
    float* hB = g_hist + basec + 8192;
    int cbase[4] = { 4 * tx, 4 * tx + 2, 32 + 4 * tx, 32 + 4 * tx + 2 };
#pragma unroll
    for (int k = 0; k < 2; k++) {
        int row  = 2 * ty + k;
        int rofw = row * 64;              // forward row offset (R)
        int rofr = (63 - row) * 64;       // reversed row offset (G, B)
#pragma unroll
        for (int m = 0; m < 4; m++) {
            int c0 = cbase[m];
            atomicAdd(hR + rofw + c0,       plo(accR[k][m]));
            atomicAdd(hR + rofw + c0 + 1,   phi(accR[k][m]));
            atomicAdd(hG + rofr + c0,       plo(accG[k][m]));
            atomicAdd(hG + rofr + c0 + 1,   phi(accG[k][m]));
            atomicAdd(hB + rofr + 63 - c0,  plo(accB[k][m]));
            atomicAdd(hB + rofr + 62 - c0,  phi(accB[k][m]));
        }
    }
}

// ---------------------------------------------------------------------------
// Kernel 2: per-batch normalize + Hellinger-style distance
// ---------------------------------------------------------------------------
__global__ void loss_kernel() {
    int b = blockIdx.x;                     // 0..7
    const float* hx = g_hist + (size_t)b * 12288;         // img 0
    const float* hy = g_hist + (size_t)(8 + b) * 12288;   // img 1
    __shared__ float red[256];
    int tid = threadIdx.x;

    float sx = 0.f, sy = 0.f;
    for (int i = tid; i < 12288; i += 256) { sx += hx[i]; sy += hy[i]; }

    red[tid] = sx; __syncthreads();
    for (int s = 128; s > 0; s >>= 1) { if (tid < s) red[tid] += red[tid + s]; __syncthreads(); }
    float Tx = red[0]; __syncthreads();

    red[tid] = sy; __syncthreads();
    for (int s = 128; s > 0; s >>= 1) { if (tid < s) red[tid] += red[tid + s]; __syncthreads(); }
    float Ty = red[0]; __syncthreads();

    float ivx = 1.0f / Tx, ivy = 1.0f / Ty;
    float acc = 0.f;
    for (int i = tid; i < 12288; i += 256) {
        float d = sqrtf(hy[i] * ivy) - sqrtf(hx[i] * ivx);
        acc = fmaf(d, d, acc);
    }
    red[tid] = acc; __syncthreads();
    for (int s = 128; s > 0; s >>= 1) { if (tid < s) red[tid] += red[tid + s]; __syncthreads(); }
    if (tid == 0) g_hn[b] = sqrtf(red[0] * 0.5f);
}

// ---------------------------------------------------------------------------
// Kernel 3: mean over batch
// ---------------------------------------------------------------------------
__global__ void final_kernel(float* out) {
    if (threadIdx.x == 0) {
        float s = 0.f;
#pragma unroll
        for (int i = 0; i < 8; i++) s += g_hn[i];
        out[0] = s * 0.125f;
    }
}

// ---------------------------------------------------------------------------
extern "C" void kernel_launch(void* const* d_in, const int* in_sizes, int n_in,
                              void* d_out, int out_size) {
    const float* x = (const float*)d_in[0];
    const float* y = (const float*)d_in[1];

    // 3 zero slices so hist_kernel is our 4th launch (global #5 incl. 2 harness
    // memsets) -> ncu -s 5 -c 1 should capture hist_kernel next round.
    const int SLICE = (HISTN + 2) / 3;
    zero_kernel<<<(SLICE + 255) / 256, 256>>>(0);
    zero_kernel<<<(SLICE + 255) / 256, 256>>>(SLICE);
    zero_kernel<<<(SLICE + 255) / 256, 256>>>(2 * SLICE);
    hist_kernel<<<16 * NCHUNK, 256>>>(x, y);
    loss_kernel<<<8, 256>>>();
    final_kernel<<<1, 32>>>((float*)d_out);
}

// round 4
// speedup vs baseline: 2.2504x; 1.8764x over previous
#include <cuda_runtime.h>

// Problem constants
#define NPIX   65536          // 256*256
#define DH     64             // histogram bins
#define PB     8              // pixels staged per SMEM round (fully unrolled)
#define NCHUNK 18             // pixel chunks per (img,b) -> 16*18 = 288 CTAs (2/SM)
#define CPX    ((NPIX + NCHUNK - 1) / NCHUNK)
#define HISTN  (2 * 8 * 3 * DH * DH)

// Scratch (allocation-free rule: __device__ globals)
__device__ float g_hist[HISTN];   // [img][b][ch][64][64]
__device__ float g_hn[8];

__device__ __forceinline__ float frcp(float x) {
    float r; asm("rcp.approx.f32 %0, %1;" : "=f"(r) : "f"(x)); return r;
}
__device__ __forceinline__ float plo(unsigned long long v) {
    return __uint_as_float((unsigned int)(v & 0xffffffffull));
}
__device__ __forceinline__ float phi(unsigned long long v) {
    return __uint_as_float((unsigned int)(v >> 32));
}

#define FFMA2(acc, a, b) asm("fma.rn.f32x2 %0, %1, %2, %0;" : "+l"(acc) : "l"(a), "l"(b))

// ---------------------------------------------------------------------------
// Kernel 0: zero a slice of the histogram scratch (3 launches keep hist_kernel
// at global launch index 5 for the ncu -s 5 -c 1 capture).
// ---------------------------------------------------------------------------
__global__ void zero_kernel(int off) {
    int i = off + blockIdx.x * blockDim.x + threadIdx.x;
    if (i < HISTN) g_hist[i] = 0.0f;
}

// ---------------------------------------------------------------------------
// Kernel 1: histogram accumulation.
// 128-thread CTAs; thread (ty,tx) owns rows {4ty..4ty+3} and cols
// {4tx..4tx+3, 32+4tx..32+4tx+3} of the 64x64 hist, all 3 channels,
// as 48 packed f32x2 accumulators.
//
// With U = iy*rbf(ur), Vi = iy*rbf(vr), V = rbf(vr), W = rbf(lg-lb):
//   accR[r][c] = sum U[r]*V[c]  = hist_r[r][c]
//   accG[r][c] = sum U[r]*W[c]  = hist_g[63-r][c]     (reverse rows at writeout)
//   accB[r][c] = sum Vi[r]*W[c] = hist_b[63-r][63-c]  (reverse both at writeout)
// ---------------------------------------------------------------------------
__global__ void __launch_bounds__(128, 2)
hist_kernel(const float* __restrict__ x, const float* __restrict__ y) {
    int combo = blockIdx.x / NCHUNK;
    int chunk = blockIdx.x % NCHUNK;
    int img = combo >> 3;
    int b   = combo & 7;
    const float* src = img ? y : x;
    const float* pr  = src + (size_t)(b * 3 + 0) * NPIX;
    const float* pg  = src + (size_t)(b * 3 + 1) * NPIX;
    const float* pbl = src + (size_t)(b * 3 + 2) * NPIX;

    int cs = chunk * CPX;
    int ce = cs + CPX; if (ce > NPIX) ce = NPIX;

    // SMEM staging. "2" arrays hold each value DUPLICATED (broadcast f32x2 pairs).
    __shared__ float  s_su2 [PB][128];  // U  = iy*rbf(ur), duplicated
    __shared__ float  s_svi2[PB][128];  // Vi = iy*rbf(vr), duplicated
    __shared__ float  s_sv  [PB][64];   // V  = rbf(vr), natural order
    __shared__ float  s_w   [PB][64];   // W  = rbf(lg-lb), natural order
    __shared__ float4 s_px  [PB];       // (ur, vr, w, iy)

    const int tid = threadIdx.x;
    const int ty  = tid >> 3;     // 0..15 -> rows 4ty..4ty+3
    const int tx  = tid & 7;      // 0..7  -> cols 4tx.. and 32+4tx..

    unsigned long long accR[4][4], accG[4][4], accB[4][4];
#pragma unroll
    for (int k = 0; k < 4; k++)
#pragma unroll
        for (int m = 0; m < 4; m++) { accR[k][m] = 0ull; accG[k][m] = 0ull; accB[k][m] = 0ull; }

    // Prefetch round 0 pixel data
    int pn = cs + tid;
    float fr = 0.f, fg = 0.f, fb = 0.f;
    if (tid < PB && pn < ce) { fr = pr[pn]; fg = pg[pn]; fb = pbl[pn]; }

    const float* su2p  = &s_su2 [0][0] + 8 * ty;
    const float* svi2p = &s_svi2[0][0] + 8 * ty;
    const float* svp   = &s_sv  [0][0] + 4 * tx;
    const float* wp    = &s_w   [0][0] + 4 * tx;

    for (int base = cs; base < ce; base += PB) {
        // ---- Stage A: per-pixel scalars from prefetched regs ----
        if (tid < PB) {
            float ur = 0.f, vr = 0.f, wv = 0.f, iy = 0.f;
            if (pn < ce) {
                float r  = fr + 1e-6f;
                float g  = fg + 1e-6f;
                float bb = fb + 1e-6f;
                float lr = __logf(r), lg = __logf(g), lb = __logf(bb);
                ur = lr - lg;
                vr = lr - lb;
                wv = lg - lb;
                iy = sqrtf(fmaf(r, r, fmaf(g, g, bb * bb)));
            }
            s_px[tid] = make_float4(ur, vr, wv, iy);   // iy=0 pad => zero contribution
        }
        __syncthreads();

        // Prefetch next round (LDG latency overlaps Stage B + C)
        if (tid < PB) {
            pn += PB;
            if (pn < ce) { fr = pr[pn]; fg = pg[pn]; fb = pbl[pn]; }
        }

        // ---- Stage B: RBF evaluation (16 threads per pixel, 4 bins each) ----
        {
            int p  = tid >> 4;            // 0..7
            int l0 = (tid & 15) << 2;
            float4 px = s_px[p];
#pragma unroll
            for (int k = 0; k < 4; k++) {
                int i = l0 + k;
                float c50 = fmaf((float)i, 300.0f / 63.0f, -150.0f);  // 50 * center_i
                float tu = fmaf(px.x, 50.0f, -c50);
                float su = px.w * frcp(fmaf(tu, tu, 1.0f));           // U
                float tv = fmaf(px.y, 50.0f, -c50);
                float sv = frcp(fmaf(tv, tv, 1.0f));                  // V
                float tw = fmaf(px.z, 50.0f, -c50);
                float sw = frcp(fmaf(tw, tw, 1.0f));                  // W
                s_sv[p][i] = sv;
                s_w [p][i] = sw;
                *(float2*)&s_su2 [p][2 * i] = make_float2(su, su);
                float vi = px.w * sv;
                *(float2*)&s_svi2[p][2 * i] = make_float2(vi, vi);    // Vi
            }
        }
        __syncthreads();

        // ---- Stage C: outer-product accumulate, fully unrolled, immediate offsets ----
#pragma unroll
        for (int p = 0; p < PB; p++) {
            ulonglong2 aU0 = *(const ulonglong2*)(su2p  + p * 128);       // rows 4ty,4ty+1 (dup)
            ulonglong2 aU1 = *(const ulonglong2*)(su2p  + p * 128 + 4);   // rows 4ty+2,4ty+3
            ulonglong2 aX0 = *(const ulonglong2*)(svi2p + p * 128);
            ulonglong2 aX1 = *(const ulonglong2*)(svi2p + p * 128 + 4);
            ulonglong2 bv0 = *(const ulonglong2*)(svp + p * 64);          // cols 4tx..4tx+3
            ulonglong2 bv1 = *(const ulonglong2*)(svp + p * 64 + 32);     // cols 32+4tx..
            ulonglong2 bw0 = *(const ulonglong2*)(wp  + p * 64);
            ulonglong2 bw1 = *(const ulonglong2*)(wp  + p * 64 + 32);

            unsigned long long rU [4] = { aU0.x, aU0.y, aU1.x, aU1.y };
            unsigned long long rVi[4] = { aX0.x, aX0.y, aX1.x, aX1.y };
            unsigned long long cV [4] = { bv0.x, bv0.y, bv1.x, bv1.y };
            unsigned long long cW [4] = { bw0.x, bw0.y, bw1.x, bw1.y };

#pragma unroll
            for (int k = 0; k < 4; k++) {
#pragma unroll
                for (int m = 0; m < 4; m++) {
                    FFMA2(accR[k][m], rU[k],  cV[m]);
                    FFMA2(accG[k][m], rU[k],  cW[m]);
                    FFMA2(accB[k][m], rVi[k], cW[m]);
                }
            }
        }
        __syncthreads();
    }

    // ---- Writeout: atomic reduce into global hist (reversals applied here) ----
    size_t basec = ((size_t)(img * 8 + b)) * 3 * 4096;
    float* hR = g_hist + basec;
    float* hG = g_hist + basec + 4096;
    float* hB = g_hist + basec + 8192;
    int cbase[4] = { 4 * tx, 4 * tx + 2, 32 + 4 * tx, 32 + 4 * tx + 2 };
#pragma unroll
    for (int k = 0; k < 4; k++) {
        int row  = 4 * ty + k;
        int rofw = row * 64;              // forward row offset (R)
        int rofr = (63 - row) * 64;       // reversed row offset (G, B)
#pragma unroll
        for (int m = 0; m < 4; m++) {
            int c0 = cbase[m];
            atomicAdd(hR + rofw + c0,       plo(accR[k][m]));
            atomicAdd(hR + rofw + c0 + 1,   phi(accR[k][m]));
            atomicAdd(hG + rofr + c0,       plo(accG[k][m]));
            atomicAdd(hG + rofr + c0 + 1,   phi(accG[k][m]));
            atomicAdd(hB + rofr + 63 - c0,  plo(accB[k][m]));
            atomicAdd(hB + rofr + 62 - c0,  phi(accB[k][m]));
        }
    }
}

// ---------------------------------------------------------------------------
// Kernel 2: per-batch normalize + Hellinger-style distance
// ---------------------------------------------------------------------------
__global__ void loss_kernel() {
    int b = blockIdx.x;                     // 0..7
    const float* hx = g_hist + (size_t)b * 12288;         // img 0
    const float* hy = g_hist + (size_t)(8 + b) * 12288;   // img 1
    __shared__ float red[256];
    int tid = threadIdx.x;

    float sx = 0.f, sy = 0.f;
    for (int i = tid; i < 12288; i += 256) { sx += hx[i]; sy += hy[i]; }

    red[tid] = sx; __syncthreads();
    for (int s = 128; s > 0; s >>= 1) { if (tid < s) red[tid] += red[tid + s]; __syncthreads(); }
    float Tx = red[0]; __syncthreads();

    red[tid] = sy; __syncthreads();
    for (int s = 128; s > 0; s >>= 1) { if (tid < s) red[tid] += red[tid + s]; __syncthreads(); }
    float Ty = red[0]; __syncthreads();

    float ivx = 1.0f / Tx, ivy = 1.0f / Ty;
    float acc = 0.f;
    for (int i = tid; i < 12288; i += 256) {
        float d = sqrtf(hy[i] * ivy) - sqrtf(hx[i] * ivx);
        acc = fmaf(d, d, acc);
    }
    red[tid] = acc; __syncthreads();
    for (int s = 128; s > 0; s >>= 1) { if (tid < s) red[tid] += red[tid + s]; __syncthreads(); }
    if (tid == 0) g_hn[b] = sqrtf(red[0] * 0.5f);
}

// ---------------------------------------------------------------------------
// Kernel 3: mean over batch
// ---------------------------------------------------------------------------
__global__ void final_kernel(float* out) {
    if (threadIdx.x == 0) {
        float s = 0.f;
#pragma unroll
        for (int i = 0; i < 8; i++) s += g_hn[i];
        out[0] = s * 0.125f;
    }
}

// ---------------------------------------------------------------------------
extern "C" void kernel_launch(void* const* d_in, const int* in_sizes, int n_in,
                              void* d_out, int out_size) {
    const float* x = (const float*)d_in[0];
    const float* y = (const float*)d_in[1];

    const int SLICE = (HISTN + 2) / 3;
    zero_kernel<<<(SLICE + 255) / 256, 256>>>(0);
    zero_kernel<<<(SLICE + 255) / 256, 256>>>(SLICE);
    zero_kernel<<<(SLICE + 255) / 256, 256>>>(2 * SLICE);
    hist_kernel<<<16 * NCHUNK, 128>>>(x, y);
    loss_kernel<<<8, 256>>>();
    final_kernel<<<1, 32>>>((float*)d_out);
}

// round 5
// speedup vs baseline: 2.4059x; 1.0691x over previous
#include <cuda_runtime.h>

// Problem constants
#define NPIX   65536          // 256*256
#define DH     64             // histogram bins
#define PB     16             // pixels staged per round
#define NCHUNK 18             // pixel chunks per (img,b) -> 16*18 = 288 CTAs (2/SM)
#define CPX    ((NPIX + NCHUNK - 1) / NCHUNK)
#define HISTN  (2 * 8 * 3 * DH * DH)

// Scratch (allocation-free rule: __device__ globals)
__device__ float g_hist[HISTN];   // [img][b][ch][64][64]
__device__ float g_hn[8];

__device__ __forceinline__ float frcp(float x) {
    float r; asm("rcp.approx.f32 %0, %1;" : "=f"(r) : "f"(x)); return r;
}
__device__ __forceinline__ float fsqrt_ap(float x) {
    float r; asm("sqrt.approx.f32 %0, %1;" : "=f"(r) : "f"(x)); return r;
}
__device__ __forceinline__ float plo(unsigned long long v) {
    return __uint_as_float((unsigned int)(v & 0xffffffffull));
}
__device__ __forceinline__ float phi(unsigned long long v) {
    return __uint_as_float((unsigned int)(v >> 32));
}

#define FFMA2(acc, a, b) asm("fma.rn.f32x2 %0, %1, %2, %0;" : "+l"(acc) : "l"(a), "l"(b))

// ---------------------------------------------------------------------------
// Kernel 0: zero a slice of the histogram scratch (3 launches keep hist_kernel
// at global launch index 5 for the ncu -s 5 -c 1 capture).
// ---------------------------------------------------------------------------
__global__ void zero_kernel(int off) {
    int i = off + blockIdx.x * blockDim.x + threadIdx.x;
    if (i < HISTN) g_hist[i] = 0.0f;
}

// ---------------------------------------------------------------------------
// Kernel 1: histogram accumulation.
// 256-thread CTAs (16 warps/SM at 2 CTAs/SM); thread (ty,tx) owns rows
// {2ty, 2ty+1} and cols {4tx..4tx+3, 32+4tx..32+4tx+3} -> 24 packed f32x2
// accumulators across the 3 channels.
//
// With U = iy*rbf(ur), Vi = iy*rbf(vr), V = rbf(vr), W = rbf(lg-lb):
//   accR[r][c] = sum U[r]*V[c]  = hist_r[r][c]
//   accG[r][c] = sum U[r]*W[c]  = hist_g[63-r][c]     (reverse rows at writeout)
//   accB[r][c] = sum Vi[r]*W[c] = hist_b[63-r][63-c]  (reverse both at writeout)
//
// Single __syncthreads per 16-pixel round: Stage B (RBF eval) writes buf[nxt]
// while Stage C (outer products) consumes buf[cur]. Pixel scalars come from a
// warp-internal shuffle of the owner lane's prefetched (r,g,b) - no Stage A.
// ---------------------------------------------------------------------------
__global__ void __launch_bounds__(256, 2)
hist_kernel(const float* __restrict__ x, const float* __restrict__ y) {
    int combo = blockIdx.x / NCHUNK;
    int chunk = blockIdx.x % NCHUNK;
    int img = combo >> 3;
    int b   = combo & 7;
    const float* src = img ? y : x;
    const float* pr  = src + (size_t)(b * 3 + 0) * NPIX;
    const float* pg  = src + (size_t)(b * 3 + 1) * NPIX;
    const float* pbl = src + (size_t)(b * 3 + 2) * NPIX;

    int cs = chunk * CPX;
    int ce = cs + CPX; if (ce > NPIX) ce = NPIX;

    // Double-buffered SMEM. "2" arrays hold each value DUPLICATED (f32x2 pairs).
    __shared__ float s_su2 [2][PB][128];  // U  = iy*rbf(ur), duplicated
    __shared__ float s_svi2[2][PB][128];  // Vi = iy*rbf(vr), duplicated
    __shared__ float s_sv  [2][PB][64];   // V  = rbf(vr), natural
    __shared__ float s_w   [2][PB][64];   // W  = rbf(lg-lb), natural

    const int tid = threadIdx.x;
    const int ty  = tid >> 3;          // 0..31 -> rows 2ty, 2ty+1
    const int tx  = tid & 7;           // 0..7  -> cols 4tx.. and 32+4tx..
    const int p   = tid >> 4;          // pixel-in-round this thread evaluates
    const int i0  = tid & 15;          // bin base (bins i0, i0+16, i0+32, i0+48)
    const bool owner = (i0 == 0);
    const int srcln  = (tid & 31) & 16;  // owner lane within warp (0 or 16)

    unsigned long long accR[2][4], accG[2][4], accB[2][4];
#pragma unroll
    for (int k = 0; k < 2; k++)
#pragma unroll
        for (int m = 0; m < 4; m++) { accR[k][m] = 0ull; accG[k][m] = 0ull; accB[k][m] = 0ull; }

    const int nr = (ce - cs + PB - 1) / PB;

    // Owner-lane prefetch registers; fr = -1 marks an invalid (pad) pixel.
    int pn = cs + p;
    float fr = -1.f, fg = 0.f, fb = 0.f;
    if (owner && pn < ce) { fr = pr[pn]; fg = pg[pn]; fb = pbl[pn]; }

    // Stage B: evaluate RBF rows for this thread's pixel into buffer nb.
    auto stageB = [&](int nb) {
        float r0 = __shfl_sync(0xffffffffu, fr, srcln);
        float g0 = __shfl_sync(0xffffffffu, fg, srcln);
        float b0 = __shfl_sync(0xffffffffu, fb, srcln);
        bool valid = (r0 >= 0.f);
        float r  = valid ? r0 + 1e-6f : 1.0f;
        float g  = valid ? g0 + 1e-6f : 1.0f;
        float bb = valid ? b0 + 1e-6f : 1.0f;
        float lr = __logf(r), lg = __logf(g), lb = __logf(bb);
        float ur = lr - lg;
        float vr = lr - lb;
        float wv = lg - lb;
        float iy = valid ? fsqrt_ap(fmaf(r, r, fmaf(g, g, bb * bb))) : 0.f;
#pragma unroll
        for (int k = 0; k < 4; k++) {
            int i = i0 + 16 * k;
            float c50 = fmaf((float)i, 300.0f / 63.0f, -150.0f);  // 50 * center_i
            float tu = fmaf(ur, 50.0f, -c50);
            float su = iy * frcp(fmaf(tu, tu, 1.0f));             // U
            float tv = fmaf(vr, 50.0f, -c50);
            float sv = frcp(fmaf(tv, tv, 1.0f));                  // V
            float tw = fmaf(wv, 50.0f, -c50);
            float sw = frcp(fmaf(tw, tw, 1.0f));                  // W
            s_sv[nb][p][i] = sv;
            s_w [nb][p][i] = sw;
            *(float2*)&s_su2 [nb][p][2 * i] = make_float2(su, su);
            float vi = iy * sv;
            *(float2*)&s_svi2[nb][p][2 * i] = make_float2(vi, vi);  // Vi
        }
    };

    // Prologue: fill buffer 0, prefetch round 1.
    stageB(0);
    pn += PB; fr = -1.f;
    if (owner && pn < ce) { fr = pr[pn]; fg = pg[pn]; fb = pbl[pn]; }
    __syncthreads();

    const float* su2b  = &s_su2 [0][0][0] + 4 * ty;
    const float* svi2b = &s_svi2[0][0][0] + 4 * ty;
    const float* svb   = &s_sv  [0][0][0] + 4 * tx;
    const float* wb    = &s_w   [0][0][0] + 4 * tx;

    for (int it = 0; it < nr; it++) {
        int cur = it & 1;
        if (it + 1 < nr) {
            stageB(cur ^ 1);
            pn += PB; fr = -1.f;
            if (owner && pn < ce) { fr = pr[pn]; fg = pg[pn]; fb = pbl[pn]; }
        }

        // Stage C: 16 pixels of outer-product accumulation from buf[cur].
        const float* su2p  = su2b  + cur * (PB * 128);
        const float* svi2p = svi2b + cur * (PB * 128);
        const float* svp   = svb   + cur * (PB * 64);
        const float* wp    = wb    + cur * (PB * 64);
#pragma unroll
        for (int q = 0; q < PB; q++) {
            ulonglong2 aU  = *(const ulonglong2*)(su2p  + q * 128);  // dup pairs rows 2ty,2ty+1
            ulonglong2 aX  = *(const ulonglong2*)(svi2p + q * 128);
            ulonglong2 bv0 = *(const ulonglong2*)(svp + q * 64);     // cols 4tx..4tx+3
            ulonglong2 bv1 = *(const ulonglong2*)(svp + q * 64 + 32);
            ulonglong2 bw0 = *(const ulonglong2*)(wp  + q * 64);
            ulonglong2 bw1 = *(const ulonglong2*)(wp  + q * 64 + 32);

            unsigned long long rU [2] = { aU.x, aU.y };
            unsigned long long rVi[2] = { aX.x, aX.y };
            unsigned long long cV [4] = { bv0.x, bv0.y, bv1.x, bv1.y };
            unsigned long long cW [4] = { bw0.x, bw0.y, bw1.x, bw1.y };

#pragma unroll
            for (int k = 0; k < 2; k++) {
#pragma unroll
                for (int m = 0; m < 4; m++) {
                    FFMA2(accR[k][m], rU[k],  cV[m]);
                    FFMA2(accG[k][m], rU[k],  cW[m]);
                    FFMA2(accB[k][m], rVi[k], cW[m]);
                }
            }
        }
        __syncthreads();
    }

    // ---- Writeout: atomic reduce into global hist (reversals applied here) ----
    size_t basec = ((size_t)(img * 8 + b)) * 3 * 4096;
    float* hR = g_hist + basec;
    float* hG = g_hist + basec + 4096;
    float* hB = g_hist + basec + 8192;
    int cbase[4] = { 4 * tx, 4 * tx + 2, 32 + 4 * tx, 32 + 4 * tx + 2 };
#pragma unroll
    for (int k = 0; k < 2; k++) {
        int row  = 2 * ty + k;
        int rofw = row * 64;              // forward row offset (R)
        int rofr = (63 - row) * 64;       // reversed row offset (G, B)
#pragma unroll
        for (int m = 0; m < 4; m++) {
            int c0 = cbase[m];
            atomicAdd(hR + rofw + c0,       plo(accR[k][m]));
            atomicAdd(hR + rofw + c0 + 1,   phi(accR[k][m]));
            atomicAdd(hG + rofr + c0,       plo(accG[k][m]));
            atomicAdd(hG + rofr + c0 + 1,   phi(accG[k][m]));
            atomicAdd(hB + rofr + 63 - c0,  plo(accB[k][m]));
            atomicAdd(hB + rofr + 62 - c0,  phi(accB[k][m]));
        }
    }
}

// ---------------------------------------------------------------------------
// Kernel 2: per-batch normalize + Hellinger-style distance
// ---------------------------------------------------------------------------
__global__ void loss_kernel() {
    int b = blockIdx.x;                     // 0..7
    const float* hx = g_hist + (size_t)b * 12288;         // img 0
    const float* hy = g_hist + (size_t)(8 + b) * 12288;   // img 1
    __shared__ float red[256];
    int tid = threadIdx.x;

    float sx = 0.f, sy = 0.f;
    for (int i = tid; i < 12288; i += 256) { sx += hx[i]; sy += hy[i]; }

    red[tid] = sx; __syncthreads();
    for (int s = 128; s > 0; s >>= 1) { if (tid < s) red[tid] += red[tid + s]; __syncthreads(); }
    float Tx = red[0]; __syncthreads();

    red[tid] = sy; __syncthreads();
    for (int s = 128; s > 0; s >>= 1) { if (tid < s) red[tid] += red[tid + s]; __syncthreads(); }
    float Ty = red[0]; __syncthreads();

    float ivx = 1.0f / Tx, ivy = 1.0f / Ty;
    float acc = 0.f;
    for (int i = tid; i < 12288; i += 256) {
        float d = sqrtf(hy[i] * ivy) - sqrtf(hx[i] * ivx);
        acc = fmaf(d, d, acc);
    }
    red[tid] = acc; __syncthreads();
    for (int s = 128; s > 0; s >>= 1) { if (tid < s) red[tid] += red[tid + s]; __syncthreads(); }
    if (tid == 0) g_hn[b] = sqrtf(red[0] * 0.5f);
}

// ---------------------------------------------------------------------------
// Kernel 3: mean over batch
// ---------------------------------------------------------------------------
__global__ void final_kernel(float* out) {
    if (threadIdx.x == 0) {
        float s = 0.f;
#pragma unroll
        for (int i = 0; i < 8; i++) s += g_hn[i];
        out[0] = s * 0.125f;
    }
}

// ---------------------------------------------------------------------------
extern "C" void kernel_launch(void* const* d_in, const int* in_sizes, int n_in,
                              void* d_out, int out_size) {
    const float* x = (const float*)d_in[0];
    const float* y = (const float*)d_in[1];

    const int SLICE = (HISTN + 2) / 3;
    zero_kernel<<<(SLICE + 255) / 256, 256>>>(0);
    zero_kernel<<<(SLICE + 255) / 256, 256>>>(SLICE);
    zero_kernel<<<(SLICE + 255) / 256, 256>>>(2 * SLICE);
    hist_kernel<<<16 * NCHUNK, 256>>>(x, y);
    loss_kernel<<<8, 256>>>();
    final_kernel<<<1, 32>>>((float*)d_out);
}